// round 13
// baseline (speedup 1.0000x reference)
#include <cuda_runtime.h>
#include <cuda_fp16.h>
#include <math.h>

#define NNODES 50000
#define KNB 32
#define NLAT 10
#define NB 4
#define NCHUNK 10
#define QROW 12500        // float4 quads per 50000-float row
#define QCHW 1250         // quads per split-K chunk (12500/10)
#define GATHER_BLOCKS 782 // ceil(50000 / 64)
#define WARMQ 5780        // total float4 quads of MLP weights to warm

__device__ uint4 g_decwr[NNODES * 2];       // fp16-packed dec_w rows (32B/row)
__device__ float g_part[NCHUNK * 800];      // GEMV partials [chunk][b*200+u]
__device__ float g_Htab[NB * 256];          // sigmoid table per (b, cluster)
__device__ float g_e[NB * NLAT];            // latent e
__device__ float g_stats[NNODES * 24];      // per-node A[10],Bv[10],S0,d2max,pad
__device__ float g_sink[WARMQ];             // L2-warm sink (deterministic writes)

__device__ __forceinline__ float2 h2f(unsigned u) {
    __half2 h = *reinterpret_cast<__half2*>(&u);
    return __half22float2(h);
}

__device__ __forceinline__ float fsigmoid(float v) {
    return 1.0f / (1.0f + __expf(-v));
}

// ---------------------------------------------------------------- k_pack
// Packs dec_w to fp16 rows AND streams the MLP weights through L2 so the
// tiny-MLP chain hits L2 instead of DRAM.
__global__ __launch_bounds__(256) void k_pack(const float* __restrict__ dec_w,
                                              const float* __restrict__ enc2_w,
                                              const float* __restrict__ h1_w,
                                              const float* __restrict__ h2_w,
                                              const float* __restrict__ h3_w) {
    int n = blockIdx.x * 256 + threadIdx.x;
    if (n < NNODES) {
        const float2* rp = (const float2*)(dec_w + n * NLAT);
        float2 a = __ldg(rp), b = __ldg(rp + 1), c = __ldg(rp + 2),
               d = __ldg(rp + 3), e = __ldg(rp + 4);
        __half2 p0 = __float22half2_rn(a), p1 = __float22half2_rn(b),
                p2 = __float22half2_rn(c), p3 = __float22half2_rn(d),
                p4 = __float22half2_rn(e);
        uint4 lo = make_uint4(*(unsigned*)&p0, *(unsigned*)&p1,
                              *(unsigned*)&p2, *(unsigned*)&p3);
        g_decwr[2 * n] = lo;
        ((uint2*)g_decwr)[4 * n + 2] = make_uint2(*(unsigned*)&p4, 0u);
    }
    // L2 warm: h3 [0,4096), h2 [4096,5120), enc2 [5120,5620), h1 [5620,5780)
    if (n < WARMQ) {
        float4 v;
        if (n < 4096)       v = __ldg((const float4*)h3_w + n);
        else if (n < 5120)  v = __ldg((const float4*)h2_w + (n - 4096));
        else if (n < 5620)  v = __ldg((const float4*)enc2_w + (n - 5120));
        else                v = __ldg((const float4*)h1_w + (n - 5620));
        g_sink[n] = (v.x + v.y) + (v.z + v.w);
    }
}

// ---------------------------------------------------------------- k_gemv
// Warp-per-u (8 u per block so the 4 x-rows are L1-shared across warps),
// split-K = 10 chunks: grid 25 x 10 = 250 blocks.
__global__ __launch_bounds__(256) void k_gemv(const float* __restrict__ x,
                                              const float* __restrict__ w) {
    int warp = threadIdx.x >> 5, lane = threadIdx.x & 31;
    int ug = blockIdx.x % 25, c = blockIdx.x / 25;
    int u = ug * 8 + warp;
    int q0 = c * QCHW;

    const float4* x4 = (const float4*)x;
    const float4* w4 = (const float4*)w + (size_t)u * QROW;

    float a0 = 0.0f, a1 = 0.0f, a2 = 0.0f, a3 = 0.0f;

#pragma unroll 2
    for (int q = q0 + lane; q < q0 + QCHW; q += 32) {
        float4 wv = __ldg(w4 + q);
        float4 x0 = __ldg(x4 + q);
        float4 x1 = __ldg(x4 + QROW + q);
        float4 x2 = __ldg(x4 + 2 * QROW + q);
        float4 x3 = __ldg(x4 + 3 * QROW + q);
        a0 = fmaf(wv.x, x0.x, a0); a0 = fmaf(wv.y, x0.y, a0);
        a0 = fmaf(wv.z, x0.z, a0); a0 = fmaf(wv.w, x0.w, a0);
        a1 = fmaf(wv.x, x1.x, a1); a1 = fmaf(wv.y, x1.y, a1);
        a1 = fmaf(wv.z, x1.z, a1); a1 = fmaf(wv.w, x1.w, a1);
        a2 = fmaf(wv.x, x2.x, a2); a2 = fmaf(wv.y, x2.y, a2);
        a2 = fmaf(wv.z, x2.z, a2); a2 = fmaf(wv.w, x2.w, a2);
        a3 = fmaf(wv.x, x3.x, a3); a3 = fmaf(wv.y, x3.y, a3);
        a3 = fmaf(wv.z, x3.z, a3); a3 = fmaf(wv.w, x3.w, a3);
    }

#pragma unroll
    for (int o = 16; o; o >>= 1) {
        a0 += __shfl_down_sync(0xffffffffu, a0, o);
        a1 += __shfl_down_sync(0xffffffffu, a1, o);
        a2 += __shfl_down_sync(0xffffffffu, a2, o);
        a3 += __shfl_down_sync(0xffffffffu, a3, o);
    }
    if (lane == 0) {
        float* p = g_part + c * 800 + u;
        p[0]   = a0;
        p[200] = a1;
        p[400] = a2;
        p[600] = a3;
    }
}

// ---------------------------------------------------------------- k_gm
// Blocks 0..781: neighbour gather -> per-node stats.
// Block 782:     the whole tiny-MLP chain (reduce+silu, e, h1, h2, h3+sig),
//                riding concurrently with the gather wave.
__global__ __launch_bounds__(256) void k_gm(const int* __restrict__ nb_id,
                                            const float* __restrict__ nb_dist,
                                            const float* __restrict__ enc1_b,
                                            const float* __restrict__ enc2_w,
                                            const float* __restrict__ enc2_b,
                                            const float* __restrict__ h1_w,
                                            const float* __restrict__ h1_b,
                                            const float* __restrict__ h2_w,
                                            const float* __restrict__ h2_b,
                                            const float* __restrict__ h3_w,
                                            const float* __restrict__ h3_b) {
    int tid = threadIdx.x;

    if (blockIdx.x >= GATHER_BLOCKS) {
        // ------------------------------------------------ MLP chain block
        __shared__ float sz[800];
        __shared__ float se[40];
        __shared__ float sh1[256];
        __shared__ float sh2[256];

        // stage 1: reduce the 10 gemv partial chunks, + bias, silu
        if (tid < 200) {
            const float4* p = (const float4*)g_part;
            float4 s = p[tid];
#pragma unroll
            for (int c = 1; c < NCHUNK; c++) {
                float4 v = p[c * 200 + tid];
                s.x += v.x; s.y += v.y; s.z += v.z; s.w += v.w;
            }
            float sv[4] = {s.x, s.y, s.z, s.w};
#pragma unroll
            for (int j = 0; j < 4; j++) {
                int idx = tid * 4 + j;
                float t = sv[j] + enc1_b[idx % 200];
                sz[idx] = t * fsigmoid(t);              // silu
            }
        }
        __syncthreads();

        // stage 2: e = z @ enc2_w.T  (40 outputs, 4 lanes each, 50 quads)
        if (tid < 160) {
            int g = tid >> 2, r = tid & 3;
            int b = g / 10, v = g - b * 10;
            const float4* wrow = (const float4*)(enc2_w + v * 200);
            const float* zb = sz + b * 200;
            float s = 0.0f;
            for (int q = r; q < 50; q += 4) {
                float4 wv = __ldg(wrow + q);
                s = fmaf(wv.x, zb[4 * q + 0], s);
                s = fmaf(wv.y, zb[4 * q + 1], s);
                s = fmaf(wv.z, zb[4 * q + 2], s);
                s = fmaf(wv.w, zb[4 * q + 3], s);
            }
#pragma unroll
            for (int o = 2; o; o >>= 1) s += __shfl_down_sync(0xffffffffu, s, o, 4);
            if (r == 0) {
                s += enc2_b[v];
                se[g] = s;
                g_e[g] = s;
            }
        }
        __syncthreads();

        // stage 3: h1
        {
            int b = tid >> 6, m = tid & 63;
            float s = h1_b[m];
#pragma unroll
            for (int v = 0; v < 10; v++)
                s = fmaf(se[b * 10 + v], h1_w[m * 10 + v], s);
            sh1[tid] = s * fsigmoid(s);
        }
        __syncthreads();

        // stage 4: h2
        {
            int b = tid >> 6, m = tid & 63;
            const float4* wrow = (const float4*)(h2_w + m * 64);
            const float* hb = sh1 + b * 64;
            float s = h2_b[m];
#pragma unroll
            for (int q = 0; q < 16; q++) {
                float4 wv = __ldg(wrow + q);
                s = fmaf(wv.x, hb[4 * q + 0], s);
                s = fmaf(wv.y, hb[4 * q + 1], s);
                s = fmaf(wv.z, hb[4 * q + 2], s);
                s = fmaf(wv.w, hb[4 * q + 3], s);
            }
            sh2[tid] = s * fsigmoid(s);
        }
        __syncthreads();

        // stage 5: h3 + sigmoid table (1024 outputs, 4 rounds of 256)
#pragma unroll
        for (int i = 0; i < 4; i++) {
            int idx = i * 256 + tid;
            int b = idx >> 8, cc = idx & 255;
            const float4* wrow = (const float4*)(h3_w + cc * 64);
            const float* hb = sh2 + b * 64;
            float s = h3_b[cc];
#pragma unroll
            for (int q = 0; q < 16; q++) {
                float4 wv = __ldg(wrow + q);
                s = fmaf(wv.x, hb[4 * q + 0], s);
                s = fmaf(wv.y, hb[4 * q + 1], s);
                s = fmaf(wv.z, hb[4 * q + 2], s);
                s = fmaf(wv.w, hb[4 * q + 3], s);
            }
            g_Htab[idx] = fsigmoid(0.005f * s);
        }
        return;
    }

    // ---------------------------------------------------- gather block
    int sub = tid & 3;
    int node = blockIdx.x * 64 + (tid >> 2);
    bool valid = (node < NNODES);
    int cnode = valid ? node : (NNODES - 1);

    float A[NLAT], Bv[NLAT];
#pragma unroll
    for (int l = 0; l < NLAT; l++) { A[l] = 0.0f; Bv[l] = 0.0f; }
    float S0 = 0.0f, d2max = 0.0f;

    const int4*   idp = (const int4*)(nb_id + cnode * KNB) + sub * 2;
    const float4* dp  = (const float4*)(nb_dist + cnode * KNB) + sub * 2;
#pragma unroll
    for (int kq = 0; kq < 2; kq++) {
        int4   iv = __ldg(idp + kq);
        float4 dv = __ldg(dp + kq);
        int   ida[4] = {iv.x, iv.y, iv.z, iv.w};
        float da[4]  = {dv.x, dv.y, dv.z, dv.w};
#pragma unroll
        for (int j = 0; j < 4; j++) {
            float d2 = da[j] * da[j];
            S0 += d2;
            d2max = fmaxf(d2max, d2);
            uint4 lo = __ldg(&g_decwr[2 * ida[j]]);
            uint2 hi = __ldg((const uint2*)g_decwr + 4 * ida[j] + 2);
            float2 f0 = h2f(lo.x), f1 = h2f(lo.y), f2 = h2f(lo.z),
                   f3 = h2f(lo.w), f4 = h2f(hi.x);
            float r[NLAT] = {f0.x, f0.y, f1.x, f1.y, f2.x,
                             f2.y, f3.x, f3.y, f4.x, f4.y};
#pragma unroll
            for (int l = 0; l < NLAT; l++) {
                A[l] += r[l];
                Bv[l] = fmaf(d2, r[l], Bv[l]);
            }
        }
    }

#pragma unroll
    for (int off = 1; off < 4; off <<= 1) {
#pragma unroll
        for (int l = 0; l < NLAT; l++) {
            A[l]  += __shfl_xor_sync(0xffffffffu, A[l],  off);
            Bv[l] += __shfl_xor_sync(0xffffffffu, Bv[l], off);
        }
        S0 += __shfl_xor_sync(0xffffffffu, S0, off);
        d2max = fmaxf(d2max, __shfl_xor_sync(0xffffffffu, d2max, off));
    }

    if (sub == 0 && valid) {
        float4* sp = (float4*)(g_stats + node * 24);
        sp[0] = make_float4(A[0], A[1], A[2], A[3]);
        sp[1] = make_float4(A[4], A[5], A[6], A[7]);
        sp[2] = make_float4(A[8], A[9], Bv[0], Bv[1]);
        sp[3] = make_float4(Bv[2], Bv[3], Bv[4], Bv[5]);
        sp[4] = make_float4(Bv[6], Bv[7], Bv[8], Bv[9]);
        sp[5] = make_float4(S0, d2max, 0.0f, 0.0f);
    }
}

// ---------------------------------------------------------------- k_final
// 1 thread per node, all 4 batches.
__global__ __launch_bounds__(256) void k_final(const int* __restrict__ labels,
                                               const float* __restrict__ dec_b,
                                               const float* __restrict__ Bparam,
                                               const int* __restrict__ nb_id,
                                               const float* __restrict__ nb_dist,
                                               const float* __restrict__ dec_w,
                                               float* __restrict__ out) {
    int node = blockIdx.x * 256 + threadIdx.x;
    if (node >= NNODES) return;

    const float4* sp = (const float4*)(g_stats + node * 24);
    float4 s0 = __ldg(sp),     s1 = __ldg(sp + 1), s2 = __ldg(sp + 2),
           s3 = __ldg(sp + 3), s4 = __ldg(sp + 4), s5 = __ldg(sp + 5);
    float A[NLAT]  = {s0.x, s0.y, s0.z, s0.w, s1.x, s1.y, s1.z, s1.w, s2.x, s2.y};
    float Bv[NLAT] = {s2.z, s2.w, s3.x, s3.y, s3.z, s3.w, s4.x, s4.y, s4.z, s4.w};
    float S0 = s5.x, d2max = s5.y;

    int label = __ldg(&labels[node]);
    float Bp = __ldg(Bparam);
    float invB2 = __fdividef(1.0f, Bp * Bp);
    float db = __ldg(&dec_b[node]);

#pragma unroll
    for (int b = 0; b < NB; b++) {
        float H = __ldg(&g_Htab[b * 256 + label]);
        float base = 1.0f - 0.5f * H;
        float ib = __fdividef(1.0f, base * base);
        float ib2 = ib * ib;
        float ib4 = ib2 * ib2;
        float inv9 = invB2 * ib4 * ib4 * ib2;

        float o = 0.0f;
        if (inv9 * d2max <= 1.0f) {
            float iw = invB2;
#pragma unroll
            for (int l = 0; l < NLAT; l++) {
                iw *= ib;
                float s = fmaf(-iw, S0, (float)KNB);
                float t = fmaf(-iw, Bv[l], A[l]);
                o = fmaf(__ldg(&g_e[b * NLAT + l]), __fdividef(t, s), o);
            }
        } else {
            // exact fallback with clamping (fp32 dec_w; practically never taken)
            float iw = invB2;
            for (int l = 0; l < NLAT; l++) {
                iw *= ib;
                float ss = 0.0f, tt = 0.0f;
                for (int k = 0; k < KNB; k++) {
                    int id = __ldg(nb_id + node * KNB + k);
                    float d = __ldg(nb_dist + node * KNB + k);
                    float d2 = d * d;
                    float win = fmaxf(0.0f, fmaf(-iw, d2, 1.0f));
                    ss += win;
                    tt = fmaf(__ldg(&dec_w[id * NLAT + l]), win, tt);
                }
                o = fmaf(__ldg(&g_e[b * NLAT + l]), __fdividef(tt, ss), o);
            }
        }
        out[b * NNODES + node] = o + db;
    }
}

// ---------------------------------------------------------------- launch
extern "C" void kernel_launch(void* const* d_in, const int* in_sizes, int n_in,
                              void* d_out, int out_size) {
    const float* x       = (const float*)d_in[0];
    const int*   nb_id   = (const int*)  d_in[1];
    const float* nb_dist = (const float*)d_in[2];
    const int*   labels  = (const int*)  d_in[3];
    const float* enc1_w  = (const float*)d_in[4];
    const float* enc1_b  = (const float*)d_in[5];
    const float* enc2_w  = (const float*)d_in[6];
    const float* enc2_b  = (const float*)d_in[7];
    const float* dec_w   = (const float*)d_in[8];
    const float* dec_b   = (const float*)d_in[9];
    const float* h1_w    = (const float*)d_in[10];
    const float* h1_b    = (const float*)d_in[11];
    const float* h2_w    = (const float*)d_in[12];
    const float* h2_b    = (const float*)d_in[13];
    const float* h3_w    = (const float*)d_in[14];
    const float* h3_b    = (const float*)d_in[15];
    const float* Bp      = (const float*)d_in[16];
    float* out = (float*)d_out;

    k_pack<<<(NNODES + 255) / 256, 256>>>(dec_w, enc2_w, h1_w, h2_w, h3_w);
    k_gemv<<<25 * NCHUNK, 256>>>(x, enc1_w);
    k_gm<<<GATHER_BLOCKS + 1, 256>>>(nb_id, nb_dist, enc1_b, enc2_w, enc2_b,
                                     h1_w, h1_b, h2_w, h2_b, h3_w, h3_b);
    k_final<<<(NNODES + 255) / 256, 256>>>(labels, dec_b, Bp, nb_id, nb_dist, dec_w, out);
}

// round 14
// speedup vs baseline: 1.0811x; 1.0811x over previous
#include <cuda_runtime.h>
#include <cuda_fp16.h>
#include <math.h>

#define NNODES 50000
#define KNB 32
#define NLAT 10
#define NB 4
#define NCHUNK 10
#define QROW 12500        // float4 quads per 50000-float row
#define QCHW 1250         // quads per split-K chunk (12500/10)
#define GATHER_BLOCKS 782 // ceil(50000 / 64)
#define WARMQ 5780        // total float4 quads of MLP weights to warm

__device__ uint4 g_decwr[NNODES * 2];       // fp16-packed dec_w rows (32B/row)
__device__ float g_part[NCHUNK * 800];      // GEMV partials [chunk][b*200+u]
__device__ float g_Htab[NB * 256];          // sigmoid table per (b, cluster)
__device__ float g_e[NB * NLAT];            // latent e
__device__ float g_stats[NNODES * 24];      // per-node A[10],Bv[10],S0,d2max,pad
__device__ float g_sink[WARMQ];             // L2-warm sink (deterministic writes)

__device__ __forceinline__ float2 h2f(unsigned u) {
    __half2 h = *reinterpret_cast<__half2*>(&u);
    return __half22float2(h);
}

__device__ __forceinline__ float fsigmoid(float v) {
    return 1.0f / (1.0f + __expf(-v));
}

// ---------------------------------------------------------------- k_pack
// Packs dec_w to fp16 rows AND streams the MLP weights through L2 so the
// tiny-MLP chain hits L2 instead of DRAM.
__global__ __launch_bounds__(256) void k_pack(const float* __restrict__ dec_w,
                                              const float* __restrict__ enc2_w,
                                              const float* __restrict__ h1_w,
                                              const float* __restrict__ h2_w,
                                              const float* __restrict__ h3_w) {
    int n = blockIdx.x * 256 + threadIdx.x;
    if (n < NNODES) {
        const float2* rp = (const float2*)(dec_w + n * NLAT);
        float2 a = __ldg(rp), b = __ldg(rp + 1), c = __ldg(rp + 2),
               d = __ldg(rp + 3), e = __ldg(rp + 4);
        __half2 p0 = __float22half2_rn(a), p1 = __float22half2_rn(b),
                p2 = __float22half2_rn(c), p3 = __float22half2_rn(d),
                p4 = __float22half2_rn(e);
        uint4 lo = make_uint4(*(unsigned*)&p0, *(unsigned*)&p1,
                              *(unsigned*)&p2, *(unsigned*)&p3);
        g_decwr[2 * n] = lo;
        ((uint2*)g_decwr)[4 * n + 2] = make_uint2(*(unsigned*)&p4, 0u);
    }
    // L2 warm: h3 [0,4096), h2 [4096,5120), enc2 [5120,5620), h1 [5620,5780)
    if (n < WARMQ) {
        float4 v;
        if (n < 4096)       v = __ldg((const float4*)h3_w + n);
        else if (n < 5120)  v = __ldg((const float4*)h2_w + (n - 4096));
        else if (n < 5620)  v = __ldg((const float4*)enc2_w + (n - 5120));
        else                v = __ldg((const float4*)h1_w + (n - 5620));
        g_sink[n] = (v.x + v.y) + (v.z + v.w);
    }
}

// ---------------------------------------------------------------- k_gemv
// Warp-per-u (8 u per block so the 4 x-rows are L1-shared across warps),
// split-K = 10 chunks: grid 25 x 10 = 250 blocks.
__global__ __launch_bounds__(256) void k_gemv(const float* __restrict__ x,
                                              const float* __restrict__ w) {
    int warp = threadIdx.x >> 5, lane = threadIdx.x & 31;
    int ug = blockIdx.x % 25, c = blockIdx.x / 25;
    int u = ug * 8 + warp;
    int q0 = c * QCHW;

    const float4* x4 = (const float4*)x;
    const float4* w4 = (const float4*)w + (size_t)u * QROW;

    float a0 = 0.0f, a1 = 0.0f, a2 = 0.0f, a3 = 0.0f;

#pragma unroll 2
    for (int q = q0 + lane; q < q0 + QCHW; q += 32) {
        float4 wv = __ldg(w4 + q);
        float4 x0 = __ldg(x4 + q);
        float4 x1 = __ldg(x4 + QROW + q);
        float4 x2 = __ldg(x4 + 2 * QROW + q);
        float4 x3 = __ldg(x4 + 3 * QROW + q);
        a0 = fmaf(wv.x, x0.x, a0); a0 = fmaf(wv.y, x0.y, a0);
        a0 = fmaf(wv.z, x0.z, a0); a0 = fmaf(wv.w, x0.w, a0);
        a1 = fmaf(wv.x, x1.x, a1); a1 = fmaf(wv.y, x1.y, a1);
        a1 = fmaf(wv.z, x1.z, a1); a1 = fmaf(wv.w, x1.w, a1);
        a2 = fmaf(wv.x, x2.x, a2); a2 = fmaf(wv.y, x2.y, a2);
        a2 = fmaf(wv.z, x2.z, a2); a2 = fmaf(wv.w, x2.w, a2);
        a3 = fmaf(wv.x, x3.x, a3); a3 = fmaf(wv.y, x3.y, a3);
        a3 = fmaf(wv.z, x3.z, a3); a3 = fmaf(wv.w, x3.w, a3);
    }

#pragma unroll
    for (int o = 16; o; o >>= 1) {
        a0 += __shfl_down_sync(0xffffffffu, a0, o);
        a1 += __shfl_down_sync(0xffffffffu, a1, o);
        a2 += __shfl_down_sync(0xffffffffu, a2, o);
        a3 += __shfl_down_sync(0xffffffffu, a3, o);
    }
    if (lane == 0) {
        float* p = g_part + c * 800 + u;
        p[0]   = a0;
        p[200] = a1;
        p[400] = a2;
        p[600] = a3;
    }
}

// ---------------------------------------------------------------- k_gm
// Block 0:       the whole tiny-MLP chain (guaranteed wave-1 resident, so it
//                overlaps the gather blocks instead of running after them).
// Blocks 1..782: neighbour gather -> per-node stats.
__global__ __launch_bounds__(256) void k_gm(const int* __restrict__ nb_id,
                                            const float* __restrict__ nb_dist,
                                            const float* __restrict__ enc1_b,
                                            const float* __restrict__ enc2_w,
                                            const float* __restrict__ enc2_b,
                                            const float* __restrict__ h1_w,
                                            const float* __restrict__ h1_b,
                                            const float* __restrict__ h2_w,
                                            const float* __restrict__ h2_b,
                                            const float* __restrict__ h3_w,
                                            const float* __restrict__ h3_b) {
    int tid = threadIdx.x;

    if (blockIdx.x == 0) {
        // ------------------------------------------------ MLP chain block
        __shared__ float sz[800];
        __shared__ float se[40];
        __shared__ float sh1[256];
        __shared__ float sh2[256];

        // stage 1: reduce the 10 gemv partial chunks, + bias, silu
        if (tid < 200) {
            const float4* p = (const float4*)g_part;
            float4 s = p[tid];
#pragma unroll
            for (int c = 1; c < NCHUNK; c++) {
                float4 v = p[c * 200 + tid];
                s.x += v.x; s.y += v.y; s.z += v.z; s.w += v.w;
            }
            float sv[4] = {s.x, s.y, s.z, s.w};
#pragma unroll
            for (int j = 0; j < 4; j++) {
                int idx = tid * 4 + j;
                float t = sv[j] + enc1_b[idx % 200];
                sz[idx] = t * fsigmoid(t);              // silu
            }
        }
        __syncthreads();

        // stage 2: e = z @ enc2_w.T  (40 outputs, 4 lanes each, 50 quads)
        if (tid < 160) {
            int g = tid >> 2, r = tid & 3;
            int b = g / 10, v = g - b * 10;
            const float4* wrow = (const float4*)(enc2_w + v * 200);
            const float* zb = sz + b * 200;
            float s = 0.0f;
            for (int q = r; q < 50; q += 4) {
                float4 wv = __ldg(wrow + q);
                s = fmaf(wv.x, zb[4 * q + 0], s);
                s = fmaf(wv.y, zb[4 * q + 1], s);
                s = fmaf(wv.z, zb[4 * q + 2], s);
                s = fmaf(wv.w, zb[4 * q + 3], s);
            }
#pragma unroll
            for (int o = 2; o; o >>= 1) s += __shfl_down_sync(0xffffffffu, s, o, 4);
            if (r == 0) {
                s += enc2_b[v];
                se[g] = s;
                g_e[g] = s;
            }
        }
        __syncthreads();

        // stage 3: h1
        {
            int b = tid >> 6, m = tid & 63;
            float s = h1_b[m];
#pragma unroll
            for (int v = 0; v < 10; v++)
                s = fmaf(se[b * 10 + v], h1_w[m * 10 + v], s);
            sh1[tid] = s * fsigmoid(s);
        }
        __syncthreads();

        // stage 4: h2
        {
            int b = tid >> 6, m = tid & 63;
            const float4* wrow = (const float4*)(h2_w + m * 64);
            const float* hb = sh1 + b * 64;
            float s = h2_b[m];
#pragma unroll
            for (int q = 0; q < 16; q++) {
                float4 wv = __ldg(wrow + q);
                s = fmaf(wv.x, hb[4 * q + 0], s);
                s = fmaf(wv.y, hb[4 * q + 1], s);
                s = fmaf(wv.z, hb[4 * q + 2], s);
                s = fmaf(wv.w, hb[4 * q + 3], s);
            }
            sh2[tid] = s * fsigmoid(s);
        }
        __syncthreads();

        // stage 5: h3 + sigmoid table (1024 outputs, 4 rounds of 256)
#pragma unroll
        for (int i = 0; i < 4; i++) {
            int idx = i * 256 + tid;
            int b = idx >> 8, cc = idx & 255;
            const float4* wrow = (const float4*)(h3_w + cc * 64);
            const float* hb = sh2 + b * 64;
            float s = h3_b[cc];
#pragma unroll
            for (int q = 0; q < 16; q++) {
                float4 wv = __ldg(wrow + q);
                s = fmaf(wv.x, hb[4 * q + 0], s);
                s = fmaf(wv.y, hb[4 * q + 1], s);
                s = fmaf(wv.z, hb[4 * q + 2], s);
                s = fmaf(wv.w, hb[4 * q + 3], s);
            }
            g_Htab[idx] = fsigmoid(0.005f * s);
        }
        return;
    }

    // ---------------------------------------------------- gather block
    int sub = tid & 3;
    int node = (blockIdx.x - 1) * 64 + (tid >> 2);
    bool valid = (node < NNODES);
    int cnode = valid ? node : (NNODES - 1);

    float A[NLAT], Bv[NLAT];
#pragma unroll
    for (int l = 0; l < NLAT; l++) { A[l] = 0.0f; Bv[l] = 0.0f; }
    float S0 = 0.0f, d2max = 0.0f;

    const int4*   idp = (const int4*)(nb_id + cnode * KNB) + sub * 2;
    const float4* dp  = (const float4*)(nb_dist + cnode * KNB) + sub * 2;
#pragma unroll
    for (int kq = 0; kq < 2; kq++) {
        int4   iv = __ldg(idp + kq);
        float4 dv = __ldg(dp + kq);
        int   ida[4] = {iv.x, iv.y, iv.z, iv.w};
        float da[4]  = {dv.x, dv.y, dv.z, dv.w};
#pragma unroll
        for (int j = 0; j < 4; j++) {
            float d2 = da[j] * da[j];
            S0 += d2;
            d2max = fmaxf(d2max, d2);
            uint4 lo = __ldg(&g_decwr[2 * ida[j]]);
            uint2 hi = __ldg((const uint2*)g_decwr + 4 * ida[j] + 2);
            float2 f0 = h2f(lo.x), f1 = h2f(lo.y), f2 = h2f(lo.z),
                   f3 = h2f(lo.w), f4 = h2f(hi.x);
            float r[NLAT] = {f0.x, f0.y, f1.x, f1.y, f2.x,
                             f2.y, f3.x, f3.y, f4.x, f4.y};
#pragma unroll
            for (int l = 0; l < NLAT; l++) {
                A[l] += r[l];
                Bv[l] = fmaf(d2, r[l], Bv[l]);
            }
        }
    }

#pragma unroll
    for (int off = 1; off < 4; off <<= 1) {
#pragma unroll
        for (int l = 0; l < NLAT; l++) {
            A[l]  += __shfl_xor_sync(0xffffffffu, A[l],  off);
            Bv[l] += __shfl_xor_sync(0xffffffffu, Bv[l], off);
        }
        S0 += __shfl_xor_sync(0xffffffffu, S0, off);
        d2max = fmaxf(d2max, __shfl_xor_sync(0xffffffffu, d2max, off));
    }

    if (sub == 0 && valid) {
        float4* sp = (float4*)(g_stats + node * 24);
        sp[0] = make_float4(A[0], A[1], A[2], A[3]);
        sp[1] = make_float4(A[4], A[5], A[6], A[7]);
        sp[2] = make_float4(A[8], A[9], Bv[0], Bv[1]);
        sp[3] = make_float4(Bv[2], Bv[3], Bv[4], Bv[5]);
        sp[4] = make_float4(Bv[6], Bv[7], Bv[8], Bv[9]);
        sp[5] = make_float4(S0, d2max, 0.0f, 0.0f);
    }
}

// ---------------------------------------------------------------- k_final
// One thread per (b, node): idx = b*NNODES + node -> coalesced stores,
// warp-local stats reads (4x redundancy stays in L1/L2), low reg pressure.
__global__ __launch_bounds__(256) void k_final(const int* __restrict__ labels,
                                               const float* __restrict__ dec_b,
                                               const float* __restrict__ Bparam,
                                               const int* __restrict__ nb_id,
                                               const float* __restrict__ nb_dist,
                                               const float* __restrict__ dec_w,
                                               float* __restrict__ out) {
    int idx = blockIdx.x * 256 + threadIdx.x;
    if (idx >= NB * NNODES) return;
    int b = idx / NNODES;
    int node = idx - b * NNODES;

    const float4* sp = (const float4*)(g_stats + node * 24);
    float4 s0 = __ldg(sp),     s1 = __ldg(sp + 1), s2 = __ldg(sp + 2),
           s3 = __ldg(sp + 3), s4 = __ldg(sp + 4), s5 = __ldg(sp + 5);
    float A[NLAT]  = {s0.x, s0.y, s0.z, s0.w, s1.x, s1.y, s1.z, s1.w, s2.x, s2.y};
    float Bv[NLAT] = {s2.z, s2.w, s3.x, s3.y, s3.z, s3.w, s4.x, s4.y, s4.z, s4.w};
    float S0 = s5.x, d2max = s5.y;

    int label = __ldg(&labels[node]);
    float Bp = __ldg(Bparam);
    float invB2 = __fdividef(1.0f, Bp * Bp);

    float H = __ldg(&g_Htab[b * 256 + label]);
    float base = 1.0f - 0.5f * H;
    float ib = __fdividef(1.0f, base * base);
    float ib2 = ib * ib;
    float ib4 = ib2 * ib2;
    float inv9 = invB2 * ib4 * ib4 * ib2;

    float o = 0.0f;
    if (inv9 * d2max <= 1.0f) {
        float iw = invB2;
#pragma unroll
        for (int l = 0; l < NLAT; l++) {
            iw *= ib;
            float s = fmaf(-iw, S0, (float)KNB);
            float t = fmaf(-iw, Bv[l], A[l]);
            o = fmaf(__ldg(&g_e[b * NLAT + l]), __fdividef(t, s), o);
        }
    } else {
        // exact fallback with clamping (fp32 dec_w; practically never taken)
        float iw = invB2;
        for (int l = 0; l < NLAT; l++) {
            iw *= ib;
            float ss = 0.0f, tt = 0.0f;
            for (int k = 0; k < KNB; k++) {
                int id = __ldg(nb_id + node * KNB + k);
                float d = __ldg(nb_dist + node * KNB + k);
                float d2 = d * d;
                float win = fmaxf(0.0f, fmaf(-iw, d2, 1.0f));
                ss += win;
                tt = fmaf(__ldg(&dec_w[id * NLAT + l]), win, tt);
            }
            o = fmaf(__ldg(&g_e[b * NLAT + l]), __fdividef(tt, ss), o);
        }
    }

    out[idx] = o + __ldg(&dec_b[node]);
}

// ---------------------------------------------------------------- launch
extern "C" void kernel_launch(void* const* d_in, const int* in_sizes, int n_in,
                              void* d_out, int out_size) {
    const float* x       = (const float*)d_in[0];
    const int*   nb_id   = (const int*)  d_in[1];
    const float* nb_dist = (const float*)d_in[2];
    const int*   labels  = (const int*)  d_in[3];
    const float* enc1_w  = (const float*)d_in[4];
    const float* enc1_b  = (const float*)d_in[5];
    const float* enc2_w  = (const float*)d_in[6];
    const float* enc2_b  = (const float*)d_in[7];
    const float* dec_w   = (const float*)d_in[8];
    const float* dec_b   = (const float*)d_in[9];
    const float* h1_w    = (const float*)d_in[10];
    const float* h1_b    = (const float*)d_in[11];
    const float* h2_w    = (const float*)d_in[12];
    const float* h2_b    = (const float*)d_in[13];
    const float* h3_w    = (const float*)d_in[14];
    const float* h3_b    = (const float*)d_in[15];
    const float* Bp      = (const float*)d_in[16];
    float* out = (float*)d_out;

    k_pack<<<(NNODES + 255) / 256, 256>>>(dec_w, enc2_w, h1_w, h2_w, h3_w);
    k_gemv<<<25 * NCHUNK, 256>>>(x, enc1_w);
    k_gm<<<GATHER_BLOCKS + 1, 256>>>(nb_id, nb_dist, enc1_b, enc2_w, enc2_b,
                                     h1_w, h1_b, h2_w, h2_b, h3_w, h3_b);
    k_final<<<(NB * NNODES + 255) / 256, 256>>>(labels, dec_b, Bp, nb_id, nb_dist, dec_w, out);
}